// round 1
// baseline (speedup 1.0000x reference)
#include <cuda_runtime.h>

// Problem constants
#define B_   64
#define C_   256        // = D (embedding dim)
#define HW_  1024       // 32*32
#define N_   65536      // B*HW tokens
#define K_   1024       // codebook size
#define D_   256
#define ZQ_ELEMS 16777216   // B*C*HW
#define GATHER_BLOCKS 2048  // N_/32

// Scratch (device globals: allocation-free rule)
__device__ float g_z2[N_];
__device__ float g_e2[K_];
__device__ int   g_idx[N_];
__device__ float g_partial[GATHER_BLOCKS];

// Packed fp32x2 FMA (Blackwell): acc = a*b + acc elementwise on the 2 lanes.
#define FMA2(acc, a, b) asm("fma.rn.f32x2 %0, %1, %2, %0;" : "+l"(acc) : "l"(a), "l"(b))

static __device__ __forceinline__ unsigned long long dup2(float x) {
    unsigned u = __float_as_uint(x);
    return ((unsigned long long)u << 32) | (unsigned long long)u;
}
static __device__ __forceinline__ float lo_f(unsigned long long v) {
    return __uint_as_float((unsigned)(v & 0xffffffffull));
}
static __device__ __forceinline__ float hi_f(unsigned long long v) {
    return __uint_as_float((unsigned)(v >> 32));
}

// ---------------------------------------------------------------------------
// z2[n] = sequential fp32 sum of fl(z^2) over the 256 channels (mimics a
// scalar-order XLA row reduction; this term's low bits gate the argmin grid).
// ---------------------------------------------------------------------------
__global__ __launch_bounds__(256) void z2_kernel(const float* __restrict__ z) {
    int n = blockIdx.x * 256 + threadIdx.x;
    if (n >= N_) return;
    int b = n >> 10, hw = n & 1023;
    const float* p = z + (size_t)b * (C_ * HW_) + hw;
    float s = 0.0f;
#pragma unroll 8
    for (int c = 0; c < C_; ++c) {
        float v = p[(size_t)c * HW_];
        s = __fadd_rn(s, __fmul_rn(v, v));     // no FMA contraction: two roundings
    }
    g_z2[n] = s;
}

// e2[k]: sequential fp32 (order-insensitive at the scales involved, ~1e-10 abs)
__global__ __launch_bounds__(256) void e2_kernel(const float* __restrict__ E) {
    int k = blockIdx.x * 256 + threadIdx.x;
    if (k >= K_) return;
    const float* p = E + (size_t)k * D_;
    float s = 0.0f;
#pragma unroll 8
    for (int c = 0; c < D_; ++c) {
        float v = p[c];
        s = __fadd_rn(s, __fmul_rn(v, v));
    }
    g_e2[k] = s;
}

// ---------------------------------------------------------------------------
// Main argmin kernel. grid = (16 token-tiles, 64 batches), 256 threads (16x16).
// Block computes S[k,t] = sum_d E[k,d]*Z[b,d,t] for 64 tokens x all 1024 k,
// in K-chunks of 64 with depth chunks of 16, using packed f32x2 FMAs.
// Each thread owns a 4k x 4t microtile (= 4k x 2 token-pairs of f32x2).
// Distances follow the reference rounding tree: fl(fl(z2+e2k) - fl(2*S)).
// ---------------------------------------------------------------------------
__global__ __launch_bounds__(256) void argmin_kernel(
    const float* __restrict__ z, const float* __restrict__ E,
    float* __restrict__ out, int out_size)
{
    __shared__ float e2s[K_];
    __shared__ float z2s[64];
    __shared__ unsigned long long EsT[16][66];  // [depth][k] duplicated {e,e}
    __shared__ float Zs[16][68];                // [depth][token]
    __shared__ float bv_s[16][64];
    __shared__ int   bi_s[16][64];

    const int tid = threadIdx.x;
    const int tx = tid & 15, ty = tid >> 4;
    const int b = blockIdx.y;
    const int tbase = blockIdx.x * 64;
    const float* zb = z + (size_t)b * (C_ * HW_);

    for (int j = tid; j < K_; j += 256) e2s[j] = g_e2[j];
    if (tid < 64) z2s[tid] = g_z2[b * HW_ + tbase + tid];

    float bestv[4];
    int   besti[4];
#pragma unroll
    for (int j = 0; j < 4; ++j) { bestv[j] = 3.4e38f; besti[j] = 0; }

    const int ekk = tid >> 2, eq = tid & 3;     // E-tile loader mapping
    const int zdd = tid >> 4, ztq = tid & 15;   // Z-tile loader mapping

    for (int kc = 0; kc < 16; ++kc) {
        const int kbase = kc * 64;
        unsigned long long acc[4][2];
#pragma unroll
        for (int i = 0; i < 4; ++i) { acc[i][0] = 0ull; acc[i][1] = 0ull; }

        for (int dc = 0; dc < 16; ++dc) {
            const int d0 = dc * 16;
            __syncthreads();
            // E tile: 64 k x 16 d, stored transposed + duplicated for f32x2
            {
                float4 ev = *(const float4*)(E + (size_t)(kbase + ekk) * D_ + d0 + eq * 4);
                EsT[eq * 4 + 0][ekk] = dup2(ev.x);
                EsT[eq * 4 + 1][ekk] = dup2(ev.y);
                EsT[eq * 4 + 2][ekk] = dup2(ev.z);
                EsT[eq * 4 + 3][ekk] = dup2(ev.w);
            }
            // Z tile: 16 d x 64 t (z is [C, HW] per batch -> rows are contiguous)
            {
                float4 zv = *(const float4*)(zb + (size_t)(d0 + zdd) * HW_ + tbase + ztq * 4);
                *(float4*)&Zs[zdd][ztq * 4] = zv;
            }
            __syncthreads();
#pragma unroll
            for (int dd = 0; dd < 16; ++dd) {
                ulonglong2 ea = *(const ulonglong2*)&EsT[dd][ty * 4];
                ulonglong2 eb = *(const ulonglong2*)&EsT[dd][ty * 4 + 2];
                ulonglong2 zz = *(const ulonglong2*)&Zs[dd][tx * 4];
                FMA2(acc[0][0], ea.x, zz.x);  FMA2(acc[0][1], ea.x, zz.y);
                FMA2(acc[1][0], ea.y, zz.x);  FMA2(acc[1][1], ea.y, zz.y);
                FMA2(acc[2][0], eb.x, zz.x);  FMA2(acc[2][1], eb.x, zz.y);
                FMA2(acc[3][0], eb.y, zz.x);  FMA2(acc[3][1], eb.y, zz.y);
            }
        }
        // distances + running argmin (reference rounding tree, no contraction)
#pragma unroll
        for (int i = 0; i < 4; ++i) {
            const int k = kbase + ty * 4 + i;
            const float e2k = e2s[k];
            float a[4];
            a[0] = lo_f(acc[i][0]); a[1] = hi_f(acc[i][0]);
            a[2] = lo_f(acc[i][1]); a[3] = hi_f(acc[i][1]);
#pragma unroll
            for (int j = 0; j < 4; ++j) {
                float d = __fsub_rn(__fadd_rn(z2s[tx * 4 + j], e2k),
                                    __fmul_rn(2.0f, a[j]));
                if (d < bestv[j]) { bestv[j] = d; besti[j] = k; }   // k ascending in-thread
            }
        }
    }

    __syncthreads();
#pragma unroll
    for (int j = 0; j < 4; ++j) {
        bv_s[ty][tx * 4 + j] = bestv[j];
        bi_s[ty][tx * 4 + j] = besti[j];
    }
    __syncthreads();
    if (tid < 64) {
        float bv = bv_s[0][tid];
        int   bi = bi_s[0][tid];
#pragma unroll
        for (int r = 1; r < 16; ++r) {
            float v = bv_s[r][tid]; int ii = bi_s[r][tid];
            // lexicographic: ties -> smallest index (jnp.argmin picks first)
            if (v < bv || (v == bv && ii < bi)) { bv = v; bi = ii; }
        }
        const int n = b * HW_ + tbase + tid;
        g_idx[n] = bi;
        if (out_size >= ZQ_ELEMS + 1 + N_)
            out[(size_t)ZQ_ELEMS + 1 + n] = (float)bi;
    }
}

// ---------------------------------------------------------------------------
// Gather z_q (with STE rounding mimic: out = fl(z + fl(e - z))), partial loss.
// One block = 32 consecutive tokens (same batch). SMEM transpose so the
// [B,C,H,W] writes are coalesced.
// ---------------------------------------------------------------------------
__global__ __launch_bounds__(256) void gather_kernel(
    const float* __restrict__ z, const float* __restrict__ E,
    float* __restrict__ out)
{
    __shared__ float Er[32][257];   // padded: bank = (i + c) % 32, conflict-free
    __shared__ int   idxs[32];
    __shared__ float red[256];

    const int tid = threadIdx.x;
    const int t0 = blockIdx.x * 32;
    const int b = t0 >> 10, hw0 = t0 & 1023;

    if (tid < 32) idxs[tid] = g_idx[t0 + tid];
    __syncthreads();

    for (int u = tid; u < 32 * 64; u += 256) {       // 32 rows x 64 float4
        int i = u >> 6, c4 = u & 63;
        float4 v = *(const float4*)(E + (size_t)idxs[i] * D_ + c4 * 4);
        Er[i][c4 * 4 + 0] = v.x; Er[i][c4 * 4 + 1] = v.y;
        Er[i][c4 * 4 + 2] = v.z; Er[i][c4 * 4 + 3] = v.w;
    }
    __syncthreads();

    float part = 0.0f;
    const int i  = tid & 31;    // token within tile
    const int cg = tid >> 5;    // channel group 0..7
    const float* zrow = z  + (size_t)b * (C_ * HW_) + hw0;
    float*       orow = out + (size_t)b * (C_ * HW_) + hw0;
    for (int c = cg; c < C_; c += 8) {
        float zv = zrow[(size_t)c * HW_ + i];
        float ev = Er[i][c];
        float df = __fsub_rn(ev, zv);
        orow[(size_t)c * HW_ + i] = __fadd_rn(zv, df);   // straight-through value
        part = __fmaf_rn(df, df, part);
    }
    red[tid] = part;
    __syncthreads();
    for (int s = 128; s > 0; s >>= 1) {
        if (tid < s) red[tid] += red[tid + s];
        __syncthreads();
    }
    if (tid == 0) g_partial[blockIdx.x] = red[0];
}

// loss = m + 0.25*m where m = mean((z_q - z)^2)  (vq == commitment numerically)
__global__ __launch_bounds__(256) void loss_kernel(float* __restrict__ out, int out_size) {
    __shared__ float red[256];
    const int tid = threadIdx.x;
    float s = 0.0f;
    for (int i = tid; i < GATHER_BLOCKS; i += 256) s += g_partial[i];
    red[tid] = s;
    __syncthreads();
    for (int st = 128; st > 0; st >>= 1) {
        if (tid < st) red[tid] += red[tid + st];
        __syncthreads();
    }
    if (tid == 0 && out_size > ZQ_ELEMS) {
        float m = red[0] / 16777216.0f;
        out[ZQ_ELEMS] = __fadd_rn(m, __fmul_rn(0.25f, m));
    }
}

extern "C" void kernel_launch(void* const* d_in, const int* in_sizes, int n_in,
                              void* d_out, int out_size) {
    const float* z = (const float*)d_in[0];   // [64,256,32,32]
    const float* E = (const float*)d_in[1];   // [1024,256]
    float* out = (float*)d_out;

    z2_kernel<<<N_ / 256, 256>>>(z);
    e2_kernel<<<K_ / 256, 256>>>(E);
    dim3 grid(16, 64);
    argmin_kernel<<<grid, 256>>>(z, E, out, out_size);
    gather_kernel<<<GATHER_BLOCKS, 256>>>(z, E, out);
    loss_kernel<<<1, 256>>>(out, out_size);
}

// round 3
// speedup vs baseline: 1.1797x; 1.1797x over previous
#include <cuda_runtime.h>

// Problem constants
#define B_   64
#define C_   256        // = D (embedding dim)
#define HW_  1024       // 32*32
#define N_   65536      // B*HW tokens
#define K_   1024       // codebook size
#define D_   256
#define ZQ_ELEMS 16777216   // B*C*HW
#define GATHER_BLOCKS 2048  // N_/32

// Scratch (device globals: allocation-free rule)
__device__ float g_e2[K_];
__device__ int   g_idx[N_];
__device__ float g_partial[GATHER_BLOCKS];

// Packed fp32x2 FMA (Blackwell): acc = a*b + acc elementwise on the 2 lanes.
#define FMA2(acc, a, b) asm("fma.rn.f32x2 %0, %1, %2, %0;" : "+l"(acc) : "l"(a), "l"(b))

static __device__ __forceinline__ unsigned long long dup2(float x) {
    unsigned u = __float_as_uint(x);
    return ((unsigned long long)u << 32) | (unsigned long long)u;
}
static __device__ __forceinline__ float lo_f(unsigned long long v) {
    return __uint_as_float((unsigned)(v & 0xffffffffull));
}
static __device__ __forceinline__ float hi_f(unsigned long long v) {
    return __uint_as_float((unsigned)(v >> 32));
}

// e2[k]: sequential fp32 (proven bit-exact in R1)
__global__ __launch_bounds__(256) void e2_kernel(const float* __restrict__ E) {
    int k = blockIdx.x * 256 + threadIdx.x;
    if (k >= K_) return;
    const float* p = E + (size_t)k * D_;
    float s = 0.0f;
#pragma unroll 8
    for (int c = 0; c < D_; ++c) {
        float v = p[c];
        s = __fadd_rn(s, __fmul_rn(v, v));
    }
    g_e2[k] = s;
}

// ---------------------------------------------------------------------------
// Argmin kernel. grid = (8 token-tiles, 64 batches), 256 threads.
// Block tile: all K=1024 (16 chunks of 64) x 128 tokens. Microtile per thread:
// 4k x 8t. Warp = 8ky x 4tx. Double-buffered smem tiles, 1 sync per stage.
// z2 computed in-block (same sequential order as before -> bit-identical).
// Numerics: per-(k,t) fp32 FMA chain sequential over d=0..255, then
// d = fl(fl(z2+e2k) - fl(2*S)); ties -> smallest k.
// ---------------------------------------------------------------------------
__global__ __launch_bounds__(256, 2) void argmin_kernel(
    const float* __restrict__ z, const float* __restrict__ E,
    float* __restrict__ out, int out_size)
{
    __shared__ __align__(16) unsigned long long EsT[2][16][66]; // [buf][d][k] dup {e,e}
    __shared__ __align__(16) float Zs[2][16][132];              // [buf][d][token]
    __shared__ float e2s[K_];
    __shared__ float z2s[128];

    const int tid  = threadIdx.x;
    const int lane = tid & 31, warp = tid >> 5;
    const int ky = ((warp & 1) << 3) | (lane >> 2);   // 0..15 (4 k each)
    const int tx = ((warp >> 1) << 2) | (lane & 3);   // 0..15 (8 t each)
    const int b = blockIdx.y;
    const int tbase = blockIdx.x * 128;
    const float* zb = z + (size_t)b * (C_ * HW_);

    // --- prologue: stage-0 tile loads into buffer 0 ---
    const int ekl = tid >> 2, edq = tid & 3;   // E loader: 64k x 4 d-quads
    {
        float4 ev = *(const float4*)(E + (size_t)ekl * D_ + edq * 4);
        EsT[0][edq * 4 + 0][ekl] = dup2(ev.x);
        EsT[0][edq * 4 + 1][ekl] = dup2(ev.y);
        EsT[0][edq * 4 + 2][ekl] = dup2(ev.z);
        EsT[0][edq * 4 + 3][ekl] = dup2(ev.w);
        const int zr = tid >> 5, zc = (tid & 31) * 4;  // Z loader: 16d x 128t
        float4 zv0 = *(const float4*)(zb + (size_t)zr * HW_ + tbase + zc);
        float4 zv1 = *(const float4*)(zb + (size_t)(zr + 8) * HW_ + tbase + zc);
        *(float4*)&Zs[0][zr][zc]     = zv0;
        *(float4*)&Zs[0][zr + 8][zc] = zv1;
    }

    // --- e2s copy + in-block z2 (identical sequential order as R1 z2) ---
    if (tid >= 128) {
        for (int j = tid - 128; j < K_; j += 128) e2s[j] = g_e2[j];
    } else {
        const float* pz = zb + tbase + tid;
        float s = 0.0f;
#pragma unroll 8
        for (int c = 0; c < C_; ++c) {
            float v = pz[(size_t)c * HW_];
            s = __fadd_rn(s, __fmul_rn(v, v));
        }
        z2s[tid] = s;
    }

    float bestv[8];
    int   besti[8];
#pragma unroll
    for (int j = 0; j < 8; ++j) { bestv[j] = 3.4e38f; besti[j] = 0; }

    unsigned long long *Ecur = &EsT[0][0][0], *Enxt = &EsT[1][0][0];
    float *Zcur = &Zs[0][0][0], *Znxt = &Zs[1][0][0];

    for (int kc = 0; kc < 16; ++kc) {
        const int kbase = kc * 64;
        unsigned long long acc[4][4];
#pragma unroll
        for (int i = 0; i < 4; ++i)
#pragma unroll
            for (int j = 0; j < 4; ++j) acc[i][j] = 0ull;

        for (int dc = 0; dc < 16; ++dc) {
            __syncthreads();   // buf cur visible; prior reads of buf nxt done

            // prefetch next stage into registers (hidden under compute)
            const int sn = kc * 16 + dc + 1;
            const bool pf = (sn < 256);
            float4 ev, zv0, zv1;
            if (pf) {
                const int nkc = sn >> 4, nd0 = (sn & 15) * 16;
                ev = *(const float4*)(E + (size_t)(nkc * 64 + ekl) * D_ + nd0 + edq * 4);
                const int zr = tid >> 5, zc = (tid & 31) * 4;
                zv0 = *(const float4*)(zb + (size_t)(nd0 + zr) * HW_ + tbase + zc);
                zv1 = *(const float4*)(zb + (size_t)(nd0 + zr + 8) * HW_ + tbase + zc);
            }

#pragma unroll
            for (int dd = 0; dd < 16; ++dd) {
                const unsigned long long* Er = Ecur + dd * 66;
                const unsigned long long* Zr =
                    (const unsigned long long*)(Zcur + dd * 132);
                ulonglong2 e01 = *(const ulonglong2*)(Er + ky * 4);
                ulonglong2 e23 = *(const ulonglong2*)(Er + ky * 4 + 2);
                ulonglong2 z01 = *(const ulonglong2*)(Zr + tx * 4);
                ulonglong2 z23 = *(const ulonglong2*)(Zr + tx * 4 + 2);
                FMA2(acc[0][0], e01.x, z01.x); FMA2(acc[0][1], e01.x, z01.y);
                FMA2(acc[0][2], e01.x, z23.x); FMA2(acc[0][3], e01.x, z23.y);
                FMA2(acc[1][0], e01.y, z01.x); FMA2(acc[1][1], e01.y, z01.y);
                FMA2(acc[1][2], e01.y, z23.x); FMA2(acc[1][3], e01.y, z23.y);
                FMA2(acc[2][0], e23.x, z01.x); FMA2(acc[2][1], e23.x, z01.y);
                FMA2(acc[2][2], e23.x, z23.x); FMA2(acc[2][3], e23.x, z23.y);
                FMA2(acc[3][0], e23.y, z01.x); FMA2(acc[3][1], e23.y, z01.y);
                FMA2(acc[3][2], e23.y, z23.x); FMA2(acc[3][3], e23.y, z23.y);
            }

            if (pf) {
                Enxt[(edq * 4 + 0) * 66 + ekl] = dup2(ev.x);
                Enxt[(edq * 4 + 1) * 66 + ekl] = dup2(ev.y);
                Enxt[(edq * 4 + 2) * 66 + ekl] = dup2(ev.z);
                Enxt[(edq * 4 + 3) * 66 + ekl] = dup2(ev.w);
                const int zr = tid >> 5, zc = (tid & 31) * 4;
                *(float4*)(Znxt + zr * 132 + zc)       = zv0;
                *(float4*)(Znxt + (zr + 8) * 132 + zc) = zv1;
            }
            { unsigned long long* t = Ecur; Ecur = Enxt; Enxt = t; }
            { float* t = Zcur; Zcur = Znxt; Znxt = t; }
        }

        // distances + running argmin (reference rounding tree, no contraction)
#pragma unroll
        for (int i = 0; i < 4; ++i) {
            const int k = kbase + ky * 4 + i;
            const float e2k = e2s[k];
#pragma unroll
            for (int j = 0; j < 4; ++j) {
                const int t0 = tx * 8 + j * 2;
                float a0 = lo_f(acc[i][j]), a1 = hi_f(acc[i][j]);
                float d0 = __fsub_rn(__fadd_rn(z2s[t0], e2k),
                                     __fmul_rn(2.0f, a0));
                float d1 = __fsub_rn(__fadd_rn(z2s[t0 + 1], e2k),
                                     __fmul_rn(2.0f, a1));
                if (d0 < bestv[j * 2])     { bestv[j * 2]     = d0; besti[j * 2]     = k; }
                if (d1 < bestv[j * 2 + 1]) { bestv[j * 2 + 1] = d1; besti[j * 2 + 1] = k; }
            }
        }
    }

    // --- cross-ky reduction (reuse tile smem) ---
    __syncthreads();
    float* rv = (float*)&EsT[0][0][0];        // 16 x 128
    int*   ri = (int*)(rv + 16 * 128);
#pragma unroll
    for (int j = 0; j < 8; ++j) {
        rv[ky * 128 + tx * 8 + j] = bestv[j];
        ri[ky * 128 + tx * 8 + j] = besti[j];
    }
    __syncthreads();
    if (tid < 128) {
        float bv = rv[tid];
        int   bi = ri[tid];
#pragma unroll
        for (int r = 1; r < 16; ++r) {
            float v = rv[r * 128 + tid]; int ii = ri[r * 128 + tid];
            if (v < bv || (v == bv && ii < bi)) { bv = v; bi = ii; }
        }
        const int n = b * HW_ + tbase + tid;
        g_idx[n] = bi;
        if (out_size >= ZQ_ELEMS + 1 + N_)
            out[(size_t)ZQ_ELEMS + 1 + n] = (float)bi;
    }
}

// ---------------------------------------------------------------------------
// Gather z_q (STE rounding mimic: out = fl(z + fl(e - z))), partial loss.
// ---------------------------------------------------------------------------
__global__ __launch_bounds__(256) void gather_kernel(
    const float* __restrict__ z, const float* __restrict__ E,
    float* __restrict__ out)
{
    __shared__ float Er[32][257];
    __shared__ int   idxs[32];
    __shared__ float red[256];

    const int tid = threadIdx.x;
    const int t0 = blockIdx.x * 32;
    const int b = t0 >> 10, hw0 = t0 & 1023;

    if (tid < 32) idxs[tid] = g_idx[t0 + tid];
    __syncthreads();

    for (int u = tid; u < 32 * 64; u += 256) {
        int i = u >> 6, c4 = u & 63;
        float4 v = *(const float4*)(E + (size_t)idxs[i] * D_ + c4 * 4);
        Er[i][c4 * 4 + 0] = v.x; Er[i][c4 * 4 + 1] = v.y;
        Er[i][c4 * 4 + 2] = v.z; Er[i][c4 * 4 + 3] = v.w;
    }
    __syncthreads();

    float part = 0.0f;
    const int i  = tid & 31;
    const int cg = tid >> 5;
    const float* zrow = z  + (size_t)b * (C_ * HW_) + hw0;
    float*       orow = out + (size_t)b * (C_ * HW_) + hw0;
    for (int c = cg; c < C_; c += 8) {
        float zv = zrow[(size_t)c * HW_ + i];
        float ev = Er[i][c];
        float df = __fsub_rn(ev, zv);
        orow[(size_t)c * HW_ + i] = __fadd_rn(zv, df);
        part = __fmaf_rn(df, df, part);
    }
    red[tid] = part;
    __syncthreads();
    for (int s = 128; s > 0; s >>= 1) {
        if (tid < s) red[tid] += red[tid + s];
        __syncthreads();
    }
    if (tid == 0) g_partial[blockIdx.x] = red[0];
}

// loss = m + 0.25*m, m = mean((z_q - z)^2)
__global__ __launch_bounds__(256) void loss_kernel(float* __restrict__ out, int out_size) {
    __shared__ float red[256];
    const int tid = threadIdx.x;
    float s = 0.0f;
    for (int i = tid; i < GATHER_BLOCKS; i += 256) s += g_partial[i];
    red[tid] = s;
    __syncthreads();
    for (int st = 128; st > 0; st >>= 1) {
        if (tid < st) red[tid] += red[tid + st];
        __syncthreads();
    }
    if (tid == 0 && out_size > ZQ_ELEMS) {
        float m = red[0] / 16777216.0f;
        out[ZQ_ELEMS] = __fadd_rn(m, __fmul_rn(0.25f, m));
    }
}

extern "C" void kernel_launch(void* const* d_in, const int* in_sizes, int n_in,
                              void* d_out, int out_size) {
    const float* z = (const float*)d_in[0];   // [64,256,32,32]
    const float* E = (const float*)d_in[1];   // [1024,256]
    float* out = (float*)d_out;

    e2_kernel<<<K_ / 256, 256>>>(E);
    dim3 grid(8, 64);
    argmin_kernel<<<grid, 256>>>(z, E, out, out_size);
    gather_kernel<<<GATHER_BLOCKS, 256>>>(z, E, out);
    loss_kernel<<<1, 256>>>(out, out_size);
}